// round 1
// baseline (speedup 1.0000x reference)
#include <cuda_runtime.h>
#include <math.h>

// Problem constants (fixed by the reference).
constexpr int B  = 4;
constexpr int T  = 1024;
constexpr int E  = 1024;
constexpr int H  = 16;
constexpr int Dh = 64;
constexpr int M  = B * T;   // 4096 rows for all projections

// Scratch (allocation-free rule: __device__ globals). 4 x 16MB.
__device__ float g_q[M * E];
__device__ float g_k[M * E];
__device__ float g_v[M * E];
__device__ float g_ctx[M * E];

// ---------------------------------------------------------------------------
// Classic 128x128x8 register-blocked SGEMM, TN form:
//   C[m][n] = (sum_k A[m][k] * W[n][k] + bias[n]) * scale
// A: [Mrows, K] row-major, W: [N, K] row-major (i.e. computes A @ W^T + b).
// 256 threads, 8x8 per-thread micro-tile.
// ---------------------------------------------------------------------------
__device__ __forceinline__ void sgemm_128x128(
    const float* __restrict__ A, const float* __restrict__ W,
    const float* __restrict__ bias, float* __restrict__ C,
    int N, int K, float scale)
{
    __shared__ float As[8][128];
    __shared__ float Ws[8][128];

    const int tid = threadIdx.x;
    const int tcx = tid & 15;      // 0..15 -> n micro
    const int tcy = tid >> 4;      // 0..15 -> m micro
    const int bm  = blockIdx.y * 128;
    const int bn  = blockIdx.x * 128;

    const int lrow = tid >> 1;         // 0..127
    const int lk   = (tid & 1) * 4;    // 0 or 4

    const float* Ag = A + (size_t)(bm + lrow) * K + lk;
    const float* Wg = W + (size_t)(bn + lrow) * K + lk;

    float acc[8][8];
#pragma unroll
    for (int i = 0; i < 8; i++)
#pragma unroll
        for (int j = 0; j < 8; j++) acc[i][j] = 0.0f;

    for (int k0 = 0; k0 < K; k0 += 8) {
        float4 a4 = *(const float4*)(Ag + k0);
        float4 w4 = *(const float4*)(Wg + k0);
        __syncthreads();   // previous iteration's compute reads done
        As[lk + 0][lrow] = a4.x; As[lk + 1][lrow] = a4.y;
        As[lk + 2][lrow] = a4.z; As[lk + 3][lrow] = a4.w;
        Ws[lk + 0][lrow] = w4.x; Ws[lk + 1][lrow] = w4.y;
        Ws[lk + 2][lrow] = w4.z; Ws[lk + 3][lrow] = w4.w;
        __syncthreads();

#pragma unroll
        for (int kk = 0; kk < 8; kk++) {
            float av[8], wv[8];
            *(float4*)&av[0] = *(const float4*)&As[kk][tcy * 8];
            *(float4*)&av[4] = *(const float4*)&As[kk][tcy * 8 + 4];
            *(float4*)&wv[0] = *(const float4*)&Ws[kk][tcx * 8];
            *(float4*)&wv[4] = *(const float4*)&Ws[kk][tcx * 8 + 4];
#pragma unroll
            for (int i = 0; i < 8; i++)
#pragma unroll
                for (int j = 0; j < 8; j++)
                    acc[i][j] += av[i] * wv[j];
        }
    }

#pragma unroll
    for (int i = 0; i < 8; i++) {
        const int m = bm + tcy * 8 + i;
#pragma unroll
        for (int j = 0; j < 8; j += 4) {
            const int n = bn + tcx * 8 + j;
            float4 o;
            o.x = (acc[i][j + 0] + bias[n + 0]) * scale;
            o.y = (acc[i][j + 1] + bias[n + 1]) * scale;
            o.z = (acc[i][j + 2] + bias[n + 2]) * scale;
            o.w = (acc[i][j + 3] + bias[n + 3]) * scale;
            *(float4*)&C[(size_t)m * N + n] = o;
        }
    }
}

// Fused QKV projection: blockIdx.z selects which projection this block does.
// Q output is pre-scaled by 1/sqrt(Dh) (matches reference's scaled q).
__global__ __launch_bounds__(256) void qkv_kernel(
    const float* __restrict__ x,
    const float* __restrict__ Wq, const float* __restrict__ bq,
    const float* __restrict__ Wk, const float* __restrict__ bk,
    const float* __restrict__ Wv, const float* __restrict__ bv)
{
    const int z = blockIdx.z;
    const float* W    = (z == 0) ? Wq : ((z == 1) ? Wk : Wv);
    const float* bias = (z == 0) ? bq : ((z == 1) ? bk : bv);
    float*       C    = (z == 0) ? g_q : ((z == 1) ? g_k : g_v);
    const float scale = (z == 0) ? 0.125f : 1.0f;   // Dh^-0.5 = 1/8
    sgemm_128x128(x, W, bias, C, E, E, scale);
}

__global__ __launch_bounds__(256) void oproj_kernel(
    const float* __restrict__ Wo, const float* __restrict__ bo,
    float* __restrict__ out)
{
    sgemm_128x128(g_ctx, Wo, bo, out, E, E, 1.0f);
}

// ---------------------------------------------------------------------------
// Flash-style attention, fp32.
// Grid: (T/64, H, B). Block: 256 threads (16x16). Each block handles 64 q-rows
// of one (b,h); loops over 64-wide K/V tiles with online softmax.
// Per-thread: 4x4 micro-tiles for both S=QK^T and O=PV.
// ---------------------------------------------------------------------------
constexpr int QS_STRIDE = 65;   // pad to soften transposed-store bank conflicts
constexpr int ATTN_SMEM_FLOATS = 2 * 64 * QS_STRIDE + 2 * 64 * 64;
constexpr int ATTN_SMEM_BYTES  = ATTN_SMEM_FLOATS * 4;   // 66048 B

__global__ __launch_bounds__(256) void attn_kernel(const float* __restrict__ mask)
{
    extern __shared__ float smem[];
    float* Qs = smem;                         // [64][QS_STRIDE], Qs[d][q]
    float* Ks = Qs + 64 * QS_STRIDE;          // [64][QS_STRIDE], Ks[d][s]
    float* Vs = Ks + 64 * QS_STRIDE;          // [64][64],        Vs[s][d]
    float* Ps = Vs + 64 * 64;                 // [64][64],        Ps[q][s]

    const int tid = threadIdx.x;
    const int tcx = tid & 15;    // -> kv col (S) / d col (O)
    const int tcy = tid >> 4;    // -> q row
    const int q0  = blockIdx.x * 64;
    const int h   = blockIdx.y;
    const int b   = blockIdx.z;

    // Load Q tile transposed: Qs[d][q] = Q[b, q0+q, h, d]
#pragma unroll
    for (int i = 0; i < 4; i++) {
        const int g  = tid + i * 256;     // 0..1023
        const int r  = g >> 4;            // q row within tile
        const int d0 = (g & 15) * 4;
        float4 v4 = *(const float4*)&g_q[(size_t)(b * T + q0 + r) * E + h * Dh + d0];
        Qs[(d0 + 0) * QS_STRIDE + r] = v4.x;
        Qs[(d0 + 1) * QS_STRIDE + r] = v4.y;
        Qs[(d0 + 2) * QS_STRIDE + r] = v4.z;
        Qs[(d0 + 3) * QS_STRIDE + r] = v4.w;
    }

    float o[4][4];
    float mrow[4], lrow[4];
    const float NEG_INF = __int_as_float(0xff800000u);
#pragma unroll
    for (int i = 0; i < 4; i++) {
        mrow[i] = NEG_INF;
        lrow[i] = 0.0f;
#pragma unroll
        for (int j = 0; j < 4; j++) o[i][j] = 0.0f;
    }

    for (int s0 = 0; s0 < T; s0 += 64) {
        __syncthreads();   // previous PV reads (and initial Q stores) done
        // Load K tile transposed Ks[d][s], V tile natural Vs[s][d]
#pragma unroll
        for (int i = 0; i < 4; i++) {
            const int g  = tid + i * 256;
            const int r  = g >> 4;
            const int d0 = (g & 15) * 4;
            float4 kv = *(const float4*)&g_k[(size_t)(b * T + s0 + r) * E + h * Dh + d0];
            Ks[(d0 + 0) * QS_STRIDE + r] = kv.x;
            Ks[(d0 + 1) * QS_STRIDE + r] = kv.y;
            Ks[(d0 + 2) * QS_STRIDE + r] = kv.z;
            Ks[(d0 + 3) * QS_STRIDE + r] = kv.w;
            float4 vv = *(const float4*)&g_v[(size_t)(b * T + s0 + r) * E + h * Dh + d0];
            *(float4*)&Vs[r * 64 + d0] = vv;
        }
        __syncthreads();

        // S = Q K^T for this tile (already scaled q)
        float sacc[4][4];
#pragma unroll
        for (int i = 0; i < 4; i++)
#pragma unroll
            for (int j = 0; j < 4; j++) sacc[i][j] = 0.0f;

#pragma unroll 8
        for (int kk = 0; kk < 64; kk++) {
            float qv[4], kvv[4];
#pragma unroll
            for (int i = 0; i < 4; i++) qv[i]  = Qs[kk * QS_STRIDE + tcy * 4 + i];
#pragma unroll
            for (int j = 0; j < 4; j++) kvv[j] = Ks[kk * QS_STRIDE + tcx * 4 + j];
#pragma unroll
            for (int i = 0; i < 4; i++)
#pragma unroll
                for (int j = 0; j < 4; j++)
                    sacc[i][j] += qv[i] * kvv[j];
        }

        // mask add + online softmax (row reductions over the 16 tcx lanes)
#pragma unroll
        for (int i = 0; i < 4; i++) {
            const int q = q0 + tcy * 4 + i;
            float4 mk = *(const float4*)&mask[((size_t)b * T + q) * T + s0 + tcx * 4];
            float sv[4];
            sv[0] = sacc[i][0] + mk.x;
            sv[1] = sacc[i][1] + mk.y;
            sv[2] = sacc[i][2] + mk.z;
            sv[3] = sacc[i][3] + mk.w;

            float tmax = fmaxf(fmaxf(sv[0], sv[1]), fmaxf(sv[2], sv[3]));
#pragma unroll
            for (int off = 8; off >= 1; off >>= 1)
                tmax = fmaxf(tmax, __shfl_xor_sync(0xffffffffu, tmax, off));

            const float mnew  = fmaxf(mrow[i], tmax);
            const float alpha = __expf(mrow[i] - mnew);
            mrow[i] = mnew;

            float p[4], ls = 0.0f;
#pragma unroll
            for (int j = 0; j < 4; j++) { p[j] = __expf(sv[j] - mnew); ls += p[j]; }
#pragma unroll
            for (int off = 8; off >= 1; off >>= 1)
                ls += __shfl_xor_sync(0xffffffffu, ls, off);

            lrow[i] = lrow[i] * alpha + ls;
#pragma unroll
            for (int j = 0; j < 4; j++) o[i][j] *= alpha;

            float4 pv = make_float4(p[0], p[1], p[2], p[3]);
            *(float4*)&Ps[(tcy * 4 + i) * 64 + tcx * 4] = pv;
        }
        __syncthreads();

        // O += P V
#pragma unroll 8
        for (int s = 0; s < 64; s++) {
            float pf[4];
#pragma unroll
            for (int i = 0; i < 4; i++) pf[i] = Ps[(tcy * 4 + i) * 64 + s];  // broadcast
            float4 vf = *(const float4*)&Vs[s * 64 + tcx * 4];
#pragma unroll
            for (int i = 0; i < 4; i++) {
                o[i][0] += pf[i] * vf.x;
                o[i][1] += pf[i] * vf.y;
                o[i][2] += pf[i] * vf.z;
                o[i][3] += pf[i] * vf.w;
            }
        }
    }

    // Normalize and write ctx[b, q, h, d]
#pragma unroll
    for (int i = 0; i < 4; i++) {
        const float inv = 1.0f / lrow[i];
        const int q = q0 + tcy * 4 + i;
        float4 ov = make_float4(o[i][0] * inv, o[i][1] * inv, o[i][2] * inv, o[i][3] * inv);
        *(float4*)&g_ctx[(size_t)(b * T + q) * E + h * Dh + tcx * 4] = ov;
    }
}

// ---------------------------------------------------------------------------
// Launch. Inputs (metadata order): hidden_states, attention_mask,
// Wq, bq, Wk, bk, Wv, bv, Wo, bo. Output: [B,T,E] float32.
// ---------------------------------------------------------------------------
extern "C" void kernel_launch(void* const* d_in, const int* in_sizes, int n_in,
                              void* d_out, int out_size)
{
    const float* x    = (const float*)d_in[0];
    const float* mask = (const float*)d_in[1];
    const float* Wq   = (const float*)d_in[2];
    const float* bq   = (const float*)d_in[3];
    const float* Wk   = (const float*)d_in[4];
    const float* bk   = (const float*)d_in[5];
    const float* Wv   = (const float*)d_in[6];
    const float* bv   = (const float*)d_in[7];
    const float* Wo   = (const float*)d_in[8];
    const float* bo   = (const float*)d_in[9];
    float* out = (float*)d_out;

    cudaFuncSetAttribute(attn_kernel,
                         cudaFuncAttributeMaxDynamicSharedMemorySize,
                         ATTN_SMEM_BYTES);

    // QKV projections: 3 GEMMs fused over blockIdx.z (768 blocks total).
    qkv_kernel<<<dim3(E / 128, M / 128, 3), 256>>>(x, Wq, bq, Wk, bk, Wv, bv);

    // Flash attention: (T/64, H, B) = (16, 16, 4) blocks.
    attn_kernel<<<dim3(T / 64, H, B), 256, ATTN_SMEM_BYTES>>>(mask);

    // Output projection.
    oproj_kernel<<<dim3(E / 128, M / 128, 1), 256>>>(Wo, bo, out);
}

// round 3
// speedup vs baseline: 1.7361x; 1.7361x over previous
#include <cuda_runtime.h>
#include <math.h>
#include <stdint.h>

// Problem constants.
constexpr int B  = 4;
constexpr int T  = 1024;
constexpr int E  = 1024;
constexpr int H  = 16;
constexpr int Dh = 64;
constexpr int M  = B * T;   // 4096

// Scratch (__device__ globals; no allocations allowed).
__device__ float g_q[M * E];
__device__ float g_k[M * E];
__device__ float g_v[M * E];
__device__ float g_ctx[M * E];

// ---------------------------------------------------------------------------
// tf32 helpers (family-generic PTX; no 'a'-target features anywhere).
// ---------------------------------------------------------------------------
__device__ __forceinline__ uint32_t tf32u(float x) {
    uint32_t u;
    asm("cvt.rn.tf32.f32 %0, %1;" : "=r"(u) : "f"(x));
    return u;
}
__device__ __forceinline__ float tf32r(float x) {
    return __uint_as_float(tf32u(x));
}

__device__ __forceinline__ void mma_tf32(float c[4], const uint32_t a[4],
                                         const uint32_t b[2])
{
    asm volatile(
        "mma.sync.aligned.m16n8k8.row.col.f32.tf32.tf32.f32 "
        "{%0,%1,%2,%3}, {%4,%5,%6,%7}, {%8,%9}, {%0,%1,%2,%3};"
        : "+f"(c[0]), "+f"(c[1]), "+f"(c[2]), "+f"(c[3])
        : "r"(a[0]), "r"(a[1]), "r"(a[2]), "r"(a[3]), "r"(b[0]), "r"(b[1]));
}

// ---------------------------------------------------------------------------
// mma.sync tf32 GEMM:  C[m][n] = (sum_k A[m][k]*W[n][k] + bias[n]) * scale
// A: [Mrows, 1024] row-major. W: [N=1024 rows, 1024] row-major (C = A @ W^T).
// CTA tile 128x128, BK=16, 256 threads = 8 warps (2 m-warps x 4 n-warps),
// warp tile 64x32 (4 m-frags x 4 n-frags of m16n8k8).
//
// SMEM holds tiles in *fragment-major* order so the compute side does clean
// LDS.128 (A) / LDS.64 (B) fetches:
//   A block (fm,fk): 32 lanes x 4 regs x 4B = 512B, padded stride 528B.
//   B block (fn,fk): 32 lanes x 2 regs x 4B = 256B, padded stride 264B.
// tf32 rounding (RN) is applied at the SMEM store.
// ---------------------------------------------------------------------------
constexpr int BM = 128, BN = 128, BK = 16;
constexpr int A_STRIDE = 528;               // bytes per A frag block
constexpr int B_STRIDE = 264;               // bytes per B frag block
constexpr int A_BYTES  = 16 * A_STRIDE;     // 8 fm x 2 fk = 8448
constexpr int B_BYTES  = 32 * B_STRIDE;     // 16 fn x 2 fk = 8448
constexpr int STG      = A_BYTES + B_BYTES; // 16896 per stage
constexpr int KITERS   = E / BK;            // 64

// Scatter one float4 (row r, k-offset k4 in tile) into A fragment layout.
__device__ __forceinline__ void stsA(char* base, int m, int k4, float4 v) {
    const int fm = m >> 4, fk = k4 >> 3, mr = m & 15;
    const int reg = (mr >> 3) + ((k4 & 4) >> 1);
    char* p = base + (fm * 2 + fk) * A_STRIDE + (mr & 7) * 64 + reg * 4;
    *(uint32_t*)(p +  0) = tf32u(v.x);
    *(uint32_t*)(p + 16) = tf32u(v.y);
    *(uint32_t*)(p + 32) = tf32u(v.z);
    *(uint32_t*)(p + 48) = tf32u(v.w);
}
__device__ __forceinline__ void stsB(char* base, int n, int k4, float4 v) {
    const int fn = n >> 3, fk = k4 >> 3;
    const int reg = (k4 & 4) >> 2;
    char* p = base + (fn * 2 + fk) * B_STRIDE + (n & 7) * 32 + reg * 4;
    *(uint32_t*)(p +  0) = tf32u(v.x);
    *(uint32_t*)(p +  8) = tf32u(v.y);
    *(uint32_t*)(p + 16) = tf32u(v.z);
    *(uint32_t*)(p + 24) = tf32u(v.w);
}

__device__ __forceinline__ void gemm_mma(
    const float* __restrict__ A, const float* __restrict__ W,
    const float* __restrict__ bias, float* __restrict__ C, float scale)
{
    __shared__ __align__(16) char sm[2 * STG];

    const int tid  = threadIdx.x;
    const int lane = tid & 31;
    const int wid  = tid >> 5;
    const int wm   = wid >> 2;          // 0..1
    const int wn   = wid & 3;           // 0..3
    const int bm   = blockIdx.y * BM;
    const int bn   = blockIdx.x * BN;

    // Per-thread gmem tile coords: idx_i = tid + 256*i, i in {0,1}
    const int m0 = tid >> 2,        k40 = (tid & 3) * 4;   // idx0
    const int m1 = (tid + 256) >> 2, k41 = k40;            // idx1 (same k4 pattern)

    const float* Arow0 = A + (size_t)(bm + m0) * E + k40;
    const float* Arow1 = A + (size_t)(bm + m1) * E + k41;
    const float* Wrow0 = W + (size_t)(bn + m0) * E + k40;
    const float* Wrow1 = W + (size_t)(bn + m1) * E + k41;

    float c[4][4][4];
#pragma unroll
    for (int i = 0; i < 4; i++)
#pragma unroll
        for (int j = 0; j < 4; j++)
#pragma unroll
            for (int r = 0; r < 4; r++) c[i][j][r] = 0.0f;

    // Stage 0 fill.
    {
        float4 a0 = *(const float4*)(Arow0);
        float4 a1 = *(const float4*)(Arow1);
        float4 b0 = *(const float4*)(Wrow0);
        float4 b1 = *(const float4*)(Wrow1);
        stsA(sm,            m0, k40, a0);
        stsA(sm,            m1, k41, a1);
        stsB(sm + A_BYTES,  m0, k40, b0);
        stsB(sm + A_BYTES,  m1, k41, b1);
    }
    __syncthreads();

    for (int it = 0; it < KITERS; it++) {
        const int cur = it & 1;
        char* bufA = sm + cur * STG;
        char* bufB = bufA + A_BYTES;

        float4 pa0, pa1, pb0, pb1;
        const bool more = (it + 1 < KITERS);
        if (more) {
            const int k0 = (it + 1) * BK;
            pa0 = *(const float4*)(Arow0 + k0);
            pa1 = *(const float4*)(Arow1 + k0);
            pb0 = *(const float4*)(Wrow0 + k0);
            pb1 = *(const float4*)(Wrow1 + k0);
        }

#pragma unroll
        for (int fk = 0; fk < 2; fk++) {
            uint32_t a[4][4], b[4][2];
#pragma unroll
            for (int im = 0; im < 4; im++) {
                uint4 t = *(const uint4*)(bufA + ((wm * 4 + im) * 2 + fk) * A_STRIDE + lane * 16);
                a[im][0] = t.x; a[im][1] = t.y; a[im][2] = t.z; a[im][3] = t.w;
            }
#pragma unroll
            for (int in = 0; in < 4; in++) {
                uint2 t = *(const uint2*)(bufB + ((wn * 4 + in) * 2 + fk) * B_STRIDE + lane * 8);
                b[in][0] = t.x; b[in][1] = t.y;
            }
#pragma unroll
            for (int im = 0; im < 4; im++)
#pragma unroll
                for (int in = 0; in < 4; in++)
                    mma_tf32(c[im][in], a[im], b[in]);
        }

        if (more) {
            char* nA = sm + (cur ^ 1) * STG;
            char* nB = nA + A_BYTES;
            stsA(nA, m0, k40, pa0);
            stsA(nA, m1, k41, pa1);
            stsB(nB, m0, k40, pb0);
            stsB(nB, m1, k41, pb1);
        }
        __syncthreads();
    }

    // Epilogue: c frag (row = lane>>2 (+8), col = 2*(lane&3) (+1)).
    const int r0 = lane >> 2;
    const int cl = 2 * (lane & 3);
#pragma unroll
    for (int im = 0; im < 4; im++) {
        const int row = bm + wm * 64 + im * 16 + r0;
#pragma unroll
        for (int in = 0; in < 4; in++) {
            const int col = bn + wn * 32 + in * 8 + cl;
            const float bb0 = bias[col], bb1 = bias[col + 1];
            float2 o0, o1;
            o0.x = (c[im][in][0] + bb0) * scale;
            o0.y = (c[im][in][1] + bb1) * scale;
            o1.x = (c[im][in][2] + bb0) * scale;
            o1.y = (c[im][in][3] + bb1) * scale;
            *(float2*)&C[(size_t)row * E + col]       = o0;
            *(float2*)&C[(size_t)(row + 8) * E + col] = o1;
        }
    }
}

__global__ __launch_bounds__(256) void qkv_mma_kernel(
    const float* __restrict__ x,
    const float* __restrict__ Wq, const float* __restrict__ bq,
    const float* __restrict__ Wk, const float* __restrict__ bk,
    const float* __restrict__ Wv, const float* __restrict__ bv)
{
    const int z = blockIdx.z;
    const float* W    = (z == 0) ? Wq : ((z == 1) ? Wk : Wv);
    const float* bias = (z == 0) ? bq : ((z == 1) ? bk : bv);
    float*       C    = (z == 0) ? g_q : ((z == 1) ? g_k : g_v);
    const float scale = (z == 0) ? 0.125f : 1.0f;     // Dh^-0.5
    gemm_mma(x, W, bias, C, scale);
}

__global__ __launch_bounds__(256) void oproj_mma_kernel(
    const float* __restrict__ Wo, const float* __restrict__ bo,
    float* __restrict__ out)
{
    gemm_mma(g_ctx, Wo, bo, out, 1.0f);
}

// ---------------------------------------------------------------------------
// Flash-style fp32 attention (proven in R1). ctx stored tf32-rounded.
// ---------------------------------------------------------------------------
constexpr int QS_STRIDE = 65;
constexpr int ATTN_SMEM_FLOATS = 2 * 64 * QS_STRIDE + 2 * 64 * 64;
constexpr int ATTN_SMEM_BYTES  = ATTN_SMEM_FLOATS * 4;

__global__ __launch_bounds__(256) void attn_kernel(const float* __restrict__ mask)
{
    extern __shared__ float fsmem[];
    float* Qs = fsmem;
    float* Ks = Qs + 64 * QS_STRIDE;
    float* Vs = Ks + 64 * QS_STRIDE;
    float* Ps = Vs + 64 * 64;

    const int tid = threadIdx.x;
    const int tcx = tid & 15;
    const int tcy = tid >> 4;
    const int q0  = blockIdx.x * 64;
    const int h   = blockIdx.y;
    const int b   = blockIdx.z;

#pragma unroll
    for (int i = 0; i < 4; i++) {
        const int g  = tid + i * 256;
        const int r  = g >> 4;
        const int d0 = (g & 15) * 4;
        float4 v4 = *(const float4*)&g_q[(size_t)(b * T + q0 + r) * E + h * Dh + d0];
        Qs[(d0 + 0) * QS_STRIDE + r] = v4.x;
        Qs[(d0 + 1) * QS_STRIDE + r] = v4.y;
        Qs[(d0 + 2) * QS_STRIDE + r] = v4.z;
        Qs[(d0 + 3) * QS_STRIDE + r] = v4.w;
    }

    float o[4][4];
    float mrow[4], lrow[4];
    const float NEG_INF = __int_as_float(0xff800000u);
#pragma unroll
    for (int i = 0; i < 4; i++) {
        mrow[i] = NEG_INF; lrow[i] = 0.0f;
#pragma unroll
        for (int j = 0; j < 4; j++) o[i][j] = 0.0f;
    }

    for (int s0 = 0; s0 < T; s0 += 64) {
        __syncthreads();
#pragma unroll
        for (int i = 0; i < 4; i++) {
            const int g  = tid + i * 256;
            const int r  = g >> 4;
            const int d0 = (g & 15) * 4;
            float4 kv = *(const float4*)&g_k[(size_t)(b * T + s0 + r) * E + h * Dh + d0];
            Ks[(d0 + 0) * QS_STRIDE + r] = kv.x;
            Ks[(d0 + 1) * QS_STRIDE + r] = kv.y;
            Ks[(d0 + 2) * QS_STRIDE + r] = kv.z;
            Ks[(d0 + 3) * QS_STRIDE + r] = kv.w;
            float4 vv = *(const float4*)&g_v[(size_t)(b * T + s0 + r) * E + h * Dh + d0];
            *(float4*)&Vs[r * 64 + d0] = vv;
        }
        __syncthreads();

        float sacc[4][4];
#pragma unroll
        for (int i = 0; i < 4; i++)
#pragma unroll
            for (int j = 0; j < 4; j++) sacc[i][j] = 0.0f;

#pragma unroll 8
        for (int kk = 0; kk < 64; kk++) {
            float qv[4], kvv[4];
#pragma unroll
            for (int i = 0; i < 4; i++) qv[i]  = Qs[kk * QS_STRIDE + tcy * 4 + i];
#pragma unroll
            for (int j = 0; j < 4; j++) kvv[j] = Ks[kk * QS_STRIDE + tcx * 4 + j];
#pragma unroll
            for (int i = 0; i < 4; i++)
#pragma unroll
                for (int j = 0; j < 4; j++)
                    sacc[i][j] += qv[i] * kvv[j];
        }

#pragma unroll
        for (int i = 0; i < 4; i++) {
            const int q = q0 + tcy * 4 + i;
            float4 mk = *(const float4*)&mask[((size_t)b * T + q) * T + s0 + tcx * 4];
            float sv[4];
            sv[0] = sacc[i][0] + mk.x;
            sv[1] = sacc[i][1] + mk.y;
            sv[2] = sacc[i][2] + mk.z;
            sv[3] = sacc[i][3] + mk.w;

            float tmax = fmaxf(fmaxf(sv[0], sv[1]), fmaxf(sv[2], sv[3]));
#pragma unroll
            for (int off = 8; off >= 1; off >>= 1)
                tmax = fmaxf(tmax, __shfl_xor_sync(0xffffffffu, tmax, off));

            const float mnew  = fmaxf(mrow[i], tmax);
            const float alpha = __expf(mrow[i] - mnew);
            mrow[i] = mnew;

            float p[4], ls = 0.0f;
#pragma unroll
            for (int j = 0; j < 4; j++) { p[j] = __expf(sv[j] - mnew); ls += p[j]; }
#pragma unroll
            for (int off = 8; off >= 1; off >>= 1)
                ls += __shfl_xor_sync(0xffffffffu, ls, off);

            lrow[i] = lrow[i] * alpha + ls;
#pragma unroll
            for (int j = 0; j < 4; j++) o[i][j] *= alpha;

            *(float4*)&Ps[(tcy * 4 + i) * 64 + tcx * 4] = make_float4(p[0], p[1], p[2], p[3]);
        }
        __syncthreads();

#pragma unroll 8
        for (int s = 0; s < 64; s++) {
            float pf[4];
#pragma unroll
            for (int i = 0; i < 4; i++) pf[i] = Ps[(tcy * 4 + i) * 64 + s];
            float4 vf = *(const float4*)&Vs[s * 64 + tcx * 4];
#pragma unroll
            for (int i = 0; i < 4; i++) {
                o[i][0] += pf[i] * vf.x;
                o[i][1] += pf[i] * vf.y;
                o[i][2] += pf[i] * vf.z;
                o[i][3] += pf[i] * vf.w;
            }
        }
    }

#pragma unroll
    for (int i = 0; i < 4; i++) {
        const float inv = 1.0f / lrow[i];
        const int q = q0 + tcy * 4 + i;
        float4 ov = make_float4(tf32r(o[i][0] * inv), tf32r(o[i][1] * inv),
                                tf32r(o[i][2] * inv), tf32r(o[i][3] * inv));
        *(float4*)&g_ctx[(size_t)(b * T + q) * E + h * Dh + tcx * 4] = ov;
    }
}

// ---------------------------------------------------------------------------
// Launch.
// ---------------------------------------------------------------------------
extern "C" void kernel_launch(void* const* d_in, const int* in_sizes, int n_in,
                              void* d_out, int out_size)
{
    const float* x    = (const float*)d_in[0];
    const float* mask = (const float*)d_in[1];
    const float* Wq   = (const float*)d_in[2];
    const float* bq   = (const float*)d_in[3];
    const float* Wk   = (const float*)d_in[4];
    const float* bk   = (const float*)d_in[5];
    const float* Wv   = (const float*)d_in[6];
    const float* bv   = (const float*)d_in[7];
    const float* Wo   = (const float*)d_in[8];
    const float* bo   = (const float*)d_in[9];
    float* out = (float*)d_out;

    cudaFuncSetAttribute(attn_kernel,
                         cudaFuncAttributeMaxDynamicSharedMemorySize,
                         ATTN_SMEM_BYTES);

    // QKV projections on mma.sync tf32 (fused over z): (8, 32, 3) CTAs.
    qkv_mma_kernel<<<dim3(E / BN, M / BM, 3), 256>>>(x, Wq, bq, Wk, bk, Wv, bv);

    // Flash attention (fp32): (16, 16, 4) CTAs.
    attn_kernel<<<dim3(T / 64, H, B), 256, ATTN_SMEM_BYTES>>>(mask);

    // Output projection: (8, 32) CTAs.
    oproj_mma_kernel<<<dim3(E / BN, M / BM, 1), 256>>>(Wo, bo, out);
}

// round 4
// speedup vs baseline: 2.4546x; 1.4138x over previous
#include <cuda_runtime.h>
#include <math.h>
#include <stdint.h>

// Problem constants.
constexpr int B  = 4;
constexpr int T  = 1024;
constexpr int E  = 1024;
constexpr int H  = 16;
constexpr int Dh = 64;
constexpr int M  = B * T;   // 4096

// Scratch (__device__ globals; no allocations allowed).
__device__ float g_q[M * E];
__device__ float g_k[M * E];
__device__ float g_v[M * E];
__device__ float g_ctx[M * E];

// ---------------------------------------------------------------------------
// tf32 helpers (family-generic PTX only).
// ---------------------------------------------------------------------------
__device__ __forceinline__ uint32_t tf32u(float x) {
    uint32_t u;
    asm("cvt.rn.tf32.f32 %0, %1;" : "=r"(u) : "f"(x));
    return u;
}
__device__ __forceinline__ float tf32r(float x) {
    return __uint_as_float(tf32u(x));
}

__device__ __forceinline__ void mma_tf32(float c[4], const uint32_t a[4],
                                         const uint32_t b[2])
{
    asm volatile(
        "mma.sync.aligned.m16n8k8.row.col.f32.tf32.tf32.f32 "
        "{%0,%1,%2,%3}, {%4,%5,%6,%7}, {%8,%9}, {%0,%1,%2,%3};"
        : "+f"(c[0]), "+f"(c[1]), "+f"(c[2]), "+f"(c[3])
        : "r"(a[0]), "r"(a[1]), "r"(a[2]), "r"(a[3]), "r"(b[0]), "r"(b[1]));
}

// Fragment-major SMEM scatter stores.
// A frag block (16m x 8k): 512B, lane l gets uint4 at l*16.
//   a0=(r=l>>2, c=l&3), a1=(r+8, c), a2=(r, c+4), a3=(r+8, c+4)
// B frag block (8k x 8n): 256B, lane l gets uint2 at l*8.
//   b0=(k=l&3, n=l>>2), b1=(k=(l&3)+4, n)
constexpr int A_STRIDE = 528;
constexpr int B_STRIDE = 264;

template <int FKN>
__device__ __forceinline__ void stsA_g(char* base, int m, int k4, float4 v) {
    const int fm = m >> 4, fk = k4 >> 3, mr = m & 15;
    const int reg = (mr >> 3) + ((k4 & 4) >> 1);
    char* p = base + (fm * FKN + fk) * A_STRIDE + (mr & 7) * 64 + reg * 4;
    *(uint32_t*)(p +  0) = tf32u(v.x);
    *(uint32_t*)(p + 16) = tf32u(v.y);
    *(uint32_t*)(p + 32) = tf32u(v.z);
    *(uint32_t*)(p + 48) = tf32u(v.w);
}
template <int FKN>
__device__ __forceinline__ void stsB_g(char* base, int n, int k4, float4 v) {
    const int fn = n >> 3, fk = k4 >> 3;
    const int reg = (k4 & 4) >> 2;
    char* p = base + (fn * FKN + fk) * B_STRIDE + (n & 7) * 32 + reg * 4;
    *(uint32_t*)(p +  0) = tf32u(v.x);
    *(uint32_t*)(p +  8) = tf32u(v.y);
    *(uint32_t*)(p + 16) = tf32u(v.z);
    *(uint32_t*)(p + 24) = tf32u(v.w);
}
// V store: element (kv=k-dim, d=n-dim), blocks ordered (fn_d * 16 + fk_kv).
__device__ __forceinline__ void stsV(char* base, int kv, int d0, float4 v) {
    const int fk = kv >> 3;
    const int fn = d0 >> 3;
    const int reg = (kv & 4) >> 2;
    char* p = base + (fn * 16 + fk) * B_STRIDE + ((d0 & 7) * 4 + (kv & 3)) * 8 + reg * 4;
    *(uint32_t*)(p +  0) = tf32u(v.x);
    *(uint32_t*)(p + 32) = tf32u(v.y);
    *(uint32_t*)(p + 64) = tf32u(v.z);
    *(uint32_t*)(p + 96) = tf32u(v.w);
}

// ---------------------------------------------------------------------------
// mma.sync tf32 GEMM (unchanged from R3):
//   C[m][n] = (sum_k A[m][k]*W[n][k] + bias[n]) * scale
// ---------------------------------------------------------------------------
constexpr int BM = 128, BN = 128, BK = 16;
constexpr int A_BYTES  = 16 * A_STRIDE;
constexpr int B_BYTES  = 32 * B_STRIDE;
constexpr int STG      = A_BYTES + B_BYTES;
constexpr int KITERS   = E / BK;

__device__ __forceinline__ void gemm_mma(
    const float* __restrict__ A, const float* __restrict__ W,
    const float* __restrict__ bias, float* __restrict__ C, float scale)
{
    __shared__ __align__(16) char sm[2 * STG];

    const int tid  = threadIdx.x;
    const int lane = tid & 31;
    const int wid  = tid >> 5;
    const int wm   = wid >> 2;
    const int wn   = wid & 3;
    const int bm   = blockIdx.y * BM;
    const int bn   = blockIdx.x * BN;

    const int m0 = tid >> 2,         k40 = (tid & 3) * 4;
    const int m1 = (tid + 256) >> 2, k41 = k40;

    const float* Arow0 = A + (size_t)(bm + m0) * E + k40;
    const float* Arow1 = A + (size_t)(bm + m1) * E + k41;
    const float* Wrow0 = W + (size_t)(bn + m0) * E + k40;
    const float* Wrow1 = W + (size_t)(bn + m1) * E + k41;

    float c[4][4][4];
#pragma unroll
    for (int i = 0; i < 4; i++)
#pragma unroll
        for (int j = 0; j < 4; j++)
#pragma unroll
            for (int r = 0; r < 4; r++) c[i][j][r] = 0.0f;

    {
        float4 a0 = *(const float4*)(Arow0);
        float4 a1 = *(const float4*)(Arow1);
        float4 b0 = *(const float4*)(Wrow0);
        float4 b1 = *(const float4*)(Wrow1);
        stsA_g<2>(sm,           m0, k40, a0);
        stsA_g<2>(sm,           m1, k41, a1);
        stsB_g<2>(sm + A_BYTES, m0, k40, b0);
        stsB_g<2>(sm + A_BYTES, m1, k41, b1);
    }
    __syncthreads();

    for (int it = 0; it < KITERS; it++) {
        const int cur = it & 1;
        char* bufA = sm + cur * STG;
        char* bufB = bufA + A_BYTES;

        float4 pa0, pa1, pb0, pb1;
        const bool more = (it + 1 < KITERS);
        if (more) {
            const int k0 = (it + 1) * BK;
            pa0 = *(const float4*)(Arow0 + k0);
            pa1 = *(const float4*)(Arow1 + k0);
            pb0 = *(const float4*)(Wrow0 + k0);
            pb1 = *(const float4*)(Wrow1 + k0);
        }

#pragma unroll
        for (int fk = 0; fk < 2; fk++) {
            uint32_t a[4][4], b[4][2];
#pragma unroll
            for (int im = 0; im < 4; im++) {
                uint4 t = *(const uint4*)(bufA + ((wm * 4 + im) * 2 + fk) * A_STRIDE + lane * 16);
                a[im][0] = t.x; a[im][1] = t.y; a[im][2] = t.z; a[im][3] = t.w;
            }
#pragma unroll
            for (int in = 0; in < 4; in++) {
                uint2 t = *(const uint2*)(bufB + ((wn * 4 + in) * 2 + fk) * B_STRIDE + lane * 8);
                b[in][0] = t.x; b[in][1] = t.y;
            }
#pragma unroll
            for (int im = 0; im < 4; im++)
#pragma unroll
                for (int in = 0; in < 4; in++)
                    mma_tf32(c[im][in], a[im], b[in]);
        }

        if (more) {
            char* nA = sm + (cur ^ 1) * STG;
            char* nB = nA + A_BYTES;
            stsA_g<2>(nA, m0, k40, pa0);
            stsA_g<2>(nA, m1, k41, pa1);
            stsB_g<2>(nB, m0, k40, pb0);
            stsB_g<2>(nB, m1, k41, pb1);
        }
        __syncthreads();
    }

    const int r0 = lane >> 2;
    const int cl = 2 * (lane & 3);
#pragma unroll
    for (int im = 0; im < 4; im++) {
        const int row = bm + wm * 64 + im * 16 + r0;
#pragma unroll
        for (int in = 0; in < 4; in++) {
            const int col = bn + wn * 32 + in * 8 + cl;
            const float bb0 = bias[col], bb1 = bias[col + 1];
            float2 o0, o1;
            o0.x = (c[im][in][0] + bb0) * scale;
            o0.y = (c[im][in][1] + bb1) * scale;
            o1.x = (c[im][in][2] + bb0) * scale;
            o1.y = (c[im][in][3] + bb1) * scale;
            *(float2*)&C[(size_t)row * E + col]       = o0;
            *(float2*)&C[(size_t)(row + 8) * E + col] = o1;
        }
    }
}

__global__ __launch_bounds__(256) void qkv_mma_kernel(
    const float* __restrict__ x,
    const float* __restrict__ Wq, const float* __restrict__ bq,
    const float* __restrict__ Wk, const float* __restrict__ bk,
    const float* __restrict__ Wv, const float* __restrict__ bv)
{
    const int z = blockIdx.z;
    const float* W    = (z == 0) ? Wq : ((z == 1) ? Wk : Wv);
    const float* bias = (z == 0) ? bq : ((z == 1) ? bk : bv);
    float*       C    = (z == 0) ? g_q : ((z == 1) ? g_k : g_v);
    const float scale = (z == 0) ? 0.125f : 1.0f;
    gemm_mma(x, W, bias, C, scale);
}

__global__ __launch_bounds__(256) void oproj_mma_kernel(
    const float* __restrict__ Wo, const float* __restrict__ bo,
    float* __restrict__ out)
{
    gemm_mma(g_ctx, Wo, bo, out, 1.0f);
}

// ---------------------------------------------------------------------------
// Tensor-core flash attention (tf32 mma.sync).
// CTA: 128 q-rows x one (b,h). 8 warps; warp w owns q rows [16w, 16w+16).
// Loop over 128-wide kv tiles: S = Q K^T (mma), mask add, online softmax in
// registers, P -> warp-private smem -> A-frags, O += P V (mma).
// ---------------------------------------------------------------------------
constexpr int PROW   = 132;                      // padded row (floats)
constexpr int SM_K_OFF    = 0;                   // 128 B-blocks
constexpr int SM_V_OFF    = 128 * B_STRIDE;      // 33792
constexpr int SM_P_OFF    = 2 * 128 * B_STRIDE;  // 67584
constexpr int SM_MASK_OFF = SM_P_OFF + 8 * 16 * PROW * 4;   // 135168
constexpr int AT_SMEM     = SM_MASK_OFF + 128 * PROW * 4;   // 202752

__global__ __launch_bounds__(256, 1) void attn_mma_kernel(const float* __restrict__ mask)
{
    extern __shared__ __align__(16) char sm[];
    char*  bufK = sm + SM_K_OFF;
    char*  bufV = sm + SM_V_OFF;
    float* Psm  = (float*)(sm + SM_P_OFF);
    float* Msm  = (float*)(sm + SM_MASK_OFF);

    const int tid  = threadIdx.x;
    const int lane = tid & 31;
    const int w    = tid >> 5;
    const int r    = lane >> 2;
    const int j    = lane & 3;
    const int q0   = blockIdx.x * 128;
    const int h    = blockIdx.y;
    const int b    = blockIdx.z;

    // Prologue: Q tile -> A-frag smem (reuses P region) -> registers.
    {
        char* bufQ = (char*)Psm;
#pragma unroll
        for (int i = 0; i < 8; i++) {
            const int idx = tid + 256 * i;
            const int row = idx >> 4, d0 = (idx & 15) * 4;
            float4 v = *(const float4*)&g_q[(size_t)(b * T + q0 + row) * E + h * Dh + d0];
            stsA_g<8>(bufQ, row, d0, v);
        }
    }
    __syncthreads();
    uint32_t qa[8][4];
    {
        const char* bufQ = (const char*)Psm;
#pragma unroll
        for (int fk = 0; fk < 8; fk++) {
            uint4 t = *(const uint4*)(bufQ + (w * 8 + fk) * A_STRIDE + lane * 16);
            qa[fk][0] = t.x; qa[fk][1] = t.y; qa[fk][2] = t.z; qa[fk][3] = t.w;
        }
    }

    float oo[8][4];
#pragma unroll
    for (int fn = 0; fn < 8; fn++)
#pragma unroll
        for (int k = 0; k < 4; k++) oo[fn][k] = 0.0f;

    const float NEG_INF = __int_as_float(0xff800000u);
    float mrow0 = NEG_INF, mrow1 = NEG_INF;
    float lrow0 = 0.0f,    lrow1 = 0.0f;

    for (int s0 = 0; s0 < T; s0 += 128) {
        __syncthreads();   // prior readers of K/V/mask/P (and Q regs) are done

        // Stage K, V (fragment-major, tf32) and mask (row-major) tiles.
#pragma unroll
        for (int i = 0; i < 8; i++) {
            const int idx = tid + 256 * i;
            const int kv = idx >> 4, d0 = (idx & 15) * 4;
            const size_t g = (size_t)(b * T + s0 + kv) * E + h * Dh + d0;
            float4 kvv = *(const float4*)&g_k[g];
            stsB_g<8>(bufK, kv, d0, kvv);
            float4 vv = *(const float4*)&g_v[g];
            stsV(bufV, kv, d0, vv);
        }
#pragma unroll
        for (int i = 0; i < 16; i++) {
            const int idx = tid + 256 * i;
            const int row = idx >> 5, c4 = (idx & 31) * 4;
            float4 mv = *(const float4*)&mask[((size_t)b * T + q0 + row) * T + s0 + c4];
            *(float4*)&Msm[row * PROW + c4] = mv;
        }
        __syncthreads();

        // S = Q K^T  (16 n-frags of 8 kv cols, 8 k-frags over Dh)
        float sc[16][4];
#pragma unroll
        for (int fn = 0; fn < 16; fn++)
#pragma unroll
            for (int k = 0; k < 4; k++) sc[fn][k] = 0.0f;

#pragma unroll
        for (int fk = 0; fk < 8; fk++) {
#pragma unroll
            for (int fn = 0; fn < 16; fn++) {
                uint2 kb = *(const uint2*)(bufK + (fn * 8 + fk) * B_STRIDE + lane * 8);
                uint32_t bb[2] = {kb.x, kb.y};
                mma_tf32(sc[fn], qa[fk], bb);
            }
        }

        // Mask add + running row max.
        float ml0 = NEG_INF, ml1 = NEG_INF;
#pragma unroll
        for (int fn = 0; fn < 16; fn++) {
            const int c0 = 8 * fn + 2 * j;
            float2 mk0 = *(const float2*)&Msm[r * PROW + c0];
            float2 mk1 = *(const float2*)&Msm[(r + 8) * PROW + c0];
            sc[fn][0] += mk0.x; sc[fn][1] += mk0.y;
            sc[fn][2] += mk1.x; sc[fn][3] += mk1.y;
            ml0 = fmaxf(ml0, fmaxf(sc[fn][0], sc[fn][1]));
            ml1 = fmaxf(ml1, fmaxf(sc[fn][2], sc[fn][3]));
        }
        ml0 = fmaxf(ml0, __shfl_xor_sync(0xffffffffu, ml0, 1));
        ml0 = fmaxf(ml0, __shfl_xor_sync(0xffffffffu, ml0, 2));
        ml1 = fmaxf(ml1, __shfl_xor_sync(0xffffffffu, ml1, 1));
        ml1 = fmaxf(ml1, __shfl_xor_sync(0xffffffffu, ml1, 2));

        const float mnew0 = fmaxf(mrow0, ml0);
        const float mnew1 = fmaxf(mrow1, ml1);
        const float alpha0 = __expf(mrow0 - mnew0);
        const float alpha1 = __expf(mrow1 - mnew1);
        mrow0 = mnew0; mrow1 = mnew1;

        // exp, P store (warp-private rows), l partial sums.
        float* Pw = Psm + w * 16 * PROW;
        float ls0 = 0.0f, ls1 = 0.0f;
#pragma unroll
        for (int fn = 0; fn < 16; fn++) {
            const int c0 = 8 * fn + 2 * j;
            float p0 = __expf(sc[fn][0] - mnew0);
            float p1 = __expf(sc[fn][1] - mnew0);
            float p2 = __expf(sc[fn][2] - mnew1);
            float p3 = __expf(sc[fn][3] - mnew1);
            ls0 += p0 + p1;
            ls1 += p2 + p3;
            uint2 u0 = {tf32u(p0), tf32u(p1)};
            uint2 u1 = {tf32u(p2), tf32u(p3)};
            *(uint2*)&Pw[r * PROW + c0]       = u0;
            *(uint2*)&Pw[(r + 8) * PROW + c0] = u1;
        }
        ls0 += __shfl_xor_sync(0xffffffffu, ls0, 1);
        ls0 += __shfl_xor_sync(0xffffffffu, ls0, 2);
        ls1 += __shfl_xor_sync(0xffffffffu, ls1, 1);
        ls1 += __shfl_xor_sync(0xffffffffu, ls1, 2);
        lrow0 = lrow0 * alpha0 + ls0;
        lrow1 = lrow1 * alpha1 + ls1;

        // Rescale O accumulators.
#pragma unroll
        for (int fn = 0; fn < 8; fn++) {
            oo[fn][0] *= alpha0; oo[fn][1] *= alpha0;
            oo[fn][2] *= alpha1; oo[fn][3] *= alpha1;
        }
        __syncwarp();

        // O += P V   (A = P from warp-private smem, B = V frags)
        const uint32_t* Pu = (const uint32_t*)Pw;
#pragma unroll
        for (int fk = 0; fk < 16; fk++) {
            uint32_t pa[4];
            pa[0] = Pu[r * PROW + 8 * fk + j];
            pa[1] = Pu[(r + 8) * PROW + 8 * fk + j];
            pa[2] = Pu[r * PROW + 8 * fk + j + 4];
            pa[3] = Pu[(r + 8) * PROW + 8 * fk + j + 4];
#pragma unroll
            for (int fn = 0; fn < 8; fn++) {
                uint2 vb = *(const uint2*)(bufV + (fn * 16 + fk) * B_STRIDE + lane * 8);
                uint32_t bb[2] = {vb.x, vb.y};
                mma_tf32(oo[fn], pa, bb);
            }
        }
    }

    // Epilogue: normalize and store ctx (tf32-rounded: it feeds tf32 oproj).
    const float inv0 = 1.0f / lrow0;
    const float inv1 = 1.0f / lrow1;
    const size_t row0 = (size_t)(b * T + q0 + w * 16 + r);
#pragma unroll
    for (int fn = 0; fn < 8; fn++) {
        const int d = h * Dh + 8 * fn + 2 * j;
        float2 v0 = {tf32r(oo[fn][0] * inv0), tf32r(oo[fn][1] * inv0)};
        float2 v1 = {tf32r(oo[fn][2] * inv1), tf32r(oo[fn][3] * inv1)};
        *(float2*)&g_ctx[row0 * E + d]       = v0;
        *(float2*)&g_ctx[(row0 + 8) * E + d] = v1;
    }
}

// ---------------------------------------------------------------------------
// Launch.
// ---------------------------------------------------------------------------
extern "C" void kernel_launch(void* const* d_in, const int* in_sizes, int n_in,
                              void* d_out, int out_size)
{
    const float* x    = (const float*)d_in[0];
    const float* mask = (const float*)d_in[1];
    const float* Wq   = (const float*)d_in[2];
    const float* bq   = (const float*)d_in[3];
    const float* Wk   = (const float*)d_in[4];
    const float* bk   = (const float*)d_in[5];
    const float* Wv   = (const float*)d_in[6];
    const float* bv   = (const float*)d_in[7];
    const float* Wo   = (const float*)d_in[8];
    const float* bo   = (const float*)d_in[9];
    float* out = (float*)d_out;

    cudaFuncSetAttribute(attn_mma_kernel,
                         cudaFuncAttributeMaxDynamicSharedMemorySize, AT_SMEM);

    // QKV projections (tf32 mma): (8, 32, 3) CTAs.
    qkv_mma_kernel<<<dim3(E / BN, M / BM, 3), 256>>>(x, Wq, bq, Wk, bk, Wv, bv);

    // Tensor-core flash attention: (8, 16, 4) CTAs.
    attn_mma_kernel<<<dim3(T / 128, H, B), 256, AT_SMEM>>>(mask);

    // Output projection: (8, 32) CTAs.
    oproj_mma_kernel<<<dim3(E / BN, M / BM, 1), 256>>>(Wo, bo, out);
}

// round 5
// speedup vs baseline: 3.0646x; 1.2485x over previous
#include <cuda_runtime.h>
#include <math.h>
#include <stdint.h>

// Problem constants.
constexpr int B  = 4;
constexpr int T  = 1024;
constexpr int E  = 1024;
constexpr int H  = 16;
constexpr int Dh = 64;
constexpr int M  = B * T;   // 4096

// Scratch (__device__ globals; no allocations allowed).
__device__ float g_q[M * E];
__device__ float g_k[M * E];
__device__ float g_v[M * E];
__device__ float g_ctx[M * E];
__device__ float g_xr[M * E];       // tf32-rounded X
__device__ float g_wr[4 * E * E];   // tf32-rounded Wq,Wk,Wv,Wo

// ---------------------------------------------------------------------------
// Helpers (family-generic PTX only: mma.sync, ldmatrix, cp.async).
// ---------------------------------------------------------------------------
__device__ __forceinline__ uint32_t smem_u32(const void* p) {
    uint32_t a;
    asm("{ .reg .u64 t; cvta.to.shared.u64 t, %1; cvt.u32.u64 %0, t; }" : "=r"(a) : "l"(p));
    return a;
}
__device__ __forceinline__ uint32_t tf32u(float x) {
    uint32_t u;
    asm("cvt.rn.tf32.f32 %0, %1;" : "=r"(u) : "f"(x));
    return u;
}
__device__ __forceinline__ float tf32r(float x) {
    return __uint_as_float(tf32u(x));
}

__device__ __forceinline__ void mma_tf32(float c[4], const uint32_t a[4],
                                         const uint32_t b[2])
{
    asm volatile(
        "mma.sync.aligned.m16n8k8.row.col.f32.tf32.tf32.f32 "
        "{%0,%1,%2,%3}, {%4,%5,%6,%7}, {%8,%9}, {%0,%1,%2,%3};"
        : "+f"(c[0]), "+f"(c[1]), "+f"(c[2]), "+f"(c[3])
        : "r"(a[0]), "r"(a[1]), "r"(a[2]), "r"(a[3]), "r"(b[0]), "r"(b[1]));
}

#define LDMX4(r0, r1, r2, r3, addr)                                        \
    asm volatile("ldmatrix.sync.aligned.m8n8.x4.shared.b16 {%0,%1,%2,%3}, [%4];" \
        : "=r"(r0), "=r"(r1), "=r"(r2), "=r"(r3) : "r"(addr))

#define CP16(dst, src) \
    asm volatile("cp.async.cg.shared.global [%0], [%1], 16;" :: "r"(dst), "l"(src))
#define CP_COMMIT() asm volatile("cp.async.commit_group;" ::: "memory")
#define CP_WAIT(n)  asm volatile("cp.async.wait_group %0;" :: "n"(n) : "memory")

// Legacy fragment-major A scatter (used only for the small Q prologue).
constexpr int A_STRIDE = 528;
template <int FKN>
__device__ __forceinline__ void stsA_g(char* base, int m, int k4, float4 v) {
    const int fm = m >> 4, fk = k4 >> 3, mr = m & 15;
    const int reg = (mr >> 3) + ((k4 & 4) >> 1);
    char* p = base + (fm * FKN + fk) * A_STRIDE + (mr & 7) * 64 + reg * 4;
    *(uint32_t*)(p +  0) = tf32u(v.x);
    *(uint32_t*)(p + 16) = tf32u(v.y);
    *(uint32_t*)(p + 32) = tf32u(v.z);
    *(uint32_t*)(p + 48) = tf32u(v.w);
}

// ---------------------------------------------------------------------------
// tf32 GEMM, cp.async 4-stage pipeline + ldmatrix.
//   C[m][n] = (sum_k A[m][k]*W[n][k] + bias[n]) * scale
// CTA 128x128, BK=16, 256 threads, warps 2x4, warp tile 64x32.
// SMEM: per stage A[128][16] + B[128][16] fp32 row-major, 16B-swizzled:
//   word w of row r lives at w ^ ((r>>1)&3).
// ---------------------------------------------------------------------------
constexpr int GA_BYTES = 128 * 16 * 4;      // 8192
constexpr int GSTG     = 2 * GA_BYTES;      // 16384
constexpr int GSTAGES  = 4;
constexpr int GEMM_SMEM = GSTAGES * GSTG;   // 65536
constexpr int GKITERS  = E / 16;            // 64

template <bool RND>
__device__ __forceinline__ void gemm_cp(
    const float* __restrict__ A, const float* __restrict__ W,
    const float* __restrict__ bias, float* __restrict__ C, float scale)
{
    extern __shared__ __align__(16) char gsm[];
    const uint32_t sb = smem_u32(gsm);

    const int tid  = threadIdx.x;
    const int lane = tid & 31;
    const int wid  = tid >> 5;
    const int wm   = wid >> 2;
    const int wn   = wid & 3;
    const int bm   = blockIdx.y * 128;
    const int bn   = blockIdx.x * 128;

    // cp.async fill coords: thread covers rows crow and crow+64, word cw.
    const int crow = tid >> 2;
    const int cw   = tid & 3;
    const float* Asrc0 = A + (size_t)(bm + crow) * E + cw * 4;
    const float* Asrc1 = A + (size_t)(bm + crow + 64) * E + cw * 4;
    const float* Wsrc0 = W + (size_t)(bn + crow) * E + cw * 4;
    const float* Wsrc1 = W + (size_t)(bn + crow + 64) * E + cw * 4;
    const uint32_t dA0 = sb + crow * 64        + (cw ^ ((crow >> 1) & 3)) * 16;
    const uint32_t dA1 = sb + (crow + 64) * 64 + (cw ^ (((crow + 64) >> 1) & 3)) * 16;

    // ldmatrix lane geometry.
    const int rA = lane & 15, hA = lane >> 4;
    const int rB = (lane & 7) | ((lane & 16) >> 1);
    const int hB = (lane >> 3) & 1;
    int arow[4], axor[4];
#pragma unroll
    for (int im = 0; im < 4; im++) {
        arow[im] = wm * 64 + im * 16 + rA;
        axor[im] = (arow[im] >> 1) & 3;
    }
    int brow[2], bxor[2];
#pragma unroll
    for (int p = 0; p < 2; p++) {
        brow[p] = wn * 32 + p * 16 + rB;
        bxor[p] = (brow[p] >> 1) & 3;
    }

    float c[4][4][4];
#pragma unroll
    for (int i = 0; i < 4; i++)
#pragma unroll
        for (int j = 0; j < 4; j++)
#pragma unroll
            for (int r = 0; r < 4; r++) c[i][j][r] = 0.0f;

    // Prologue: stages 0..2.
#pragma unroll
    for (int st = 0; st < 3; st++) {
        const uint32_t base = st * GSTG;
        const int koff = st * 16;
        CP16(dA0 + base,            Asrc0 + koff);
        CP16(dA1 + base,            Asrc1 + koff);
        CP16(dA0 + base + GA_BYTES, Wsrc0 + koff);
        CP16(dA1 + base + GA_BYTES, Wsrc1 + koff);
        CP_COMMIT();
    }

    for (int it = 0; it < GKITERS; it++) {
        if (it < GKITERS - 2)      CP_WAIT(2);
        else if (it == GKITERS - 2) CP_WAIT(1);
        else                        CP_WAIT(0);
        __syncthreads();

        if (it + 3 < GKITERS) {
            const uint32_t base = ((it + 3) & 3) * GSTG;
            const int koff = (it + 3) * 16;
            CP16(dA0 + base,            Asrc0 + koff);
            CP16(dA1 + base,            Asrc1 + koff);
            CP16(dA0 + base + GA_BYTES, Wsrc0 + koff);
            CP16(dA1 + base + GA_BYTES, Wsrc1 + koff);
            CP_COMMIT();
        }

        const uint32_t abase = sb + (it & 3) * GSTG;
        const uint32_t bbase = abase + GA_BYTES;
#pragma unroll
        for (int fk = 0; fk < 2; fk++) {
            uint32_t a[4][4], b[4][2];
#pragma unroll
            for (int im = 0; im < 4; im++) {
                const int sw = (2 * fk + hA) ^ axor[im];
                LDMX4(a[im][0], a[im][1], a[im][2], a[im][3],
                      abase + arow[im] * 64 + sw * 16);
            }
#pragma unroll
            for (int p = 0; p < 2; p++) {
                const int sw = (2 * fk + hB) ^ bxor[p];
                LDMX4(b[2 * p][0], b[2 * p][1], b[2 * p + 1][0], b[2 * p + 1][1],
                      bbase + brow[p] * 64 + sw * 16);
            }
#pragma unroll
            for (int im = 0; im < 4; im++)
#pragma unroll
                for (int in = 0; in < 4; in++)
                    mma_tf32(c[im][in], a[im], b[in]);
        }
        __syncthreads();
    }

    // Epilogue.
    const int r0 = lane >> 2;
    const int cl = 2 * (lane & 3);
#pragma unroll
    for (int im = 0; im < 4; im++) {
        const int row = bm + wm * 64 + im * 16 + r0;
#pragma unroll
        for (int in = 0; in < 4; in++) {
            const int col = bn + wn * 32 + in * 8 + cl;
            const float bb0 = bias[col], bb1 = bias[col + 1];
            float2 o0, o1;
            o0.x = (c[im][in][0] + bb0) * scale;
            o0.y = (c[im][in][1] + bb1) * scale;
            o1.x = (c[im][in][2] + bb0) * scale;
            o1.y = (c[im][in][3] + bb1) * scale;
            if (RND) {
                o0.x = tf32r(o0.x); o0.y = tf32r(o0.y);
                o1.x = tf32r(o1.x); o1.y = tf32r(o1.y);
            }
            *(float2*)&C[(size_t)row * E + col]       = o0;
            *(float2*)&C[(size_t)(row + 8) * E + col] = o1;
        }
    }
}

__global__ __launch_bounds__(256) void qkv_mma_kernel(
    const float* __restrict__ bq, const float* __restrict__ bk,
    const float* __restrict__ bv)
{
    const int z = blockIdx.z;
    const float* W    = g_wr + (size_t)z * E * E;
    const float* bias = (z == 0) ? bq : ((z == 1) ? bk : bv);
    float*       C    = (z == 0) ? g_q : ((z == 1) ? g_k : g_v);
    const float scale = (z == 0) ? 0.125f : 1.0f;     // Dh^-0.5
    gemm_cp<true>(g_xr, W, bias, C, scale);
}

__global__ __launch_bounds__(256) void oproj_mma_kernel(
    const float* __restrict__ bo, float* __restrict__ out)
{
    gemm_cp<false>(g_ctx, g_wr + (size_t)3 * E * E, bo, out, 1.0f);
}

// ---------------------------------------------------------------------------
// tf32-RN pre-round of X and the 4 weight matrices (one launch).
// ---------------------------------------------------------------------------
__global__ __launch_bounds__(256) void round5_kernel(
    const float* __restrict__ x,  const float* __restrict__ wq,
    const float* __restrict__ wk, const float* __restrict__ wv,
    const float* __restrict__ wo)
{
    const float* src; float* dst; int n4;
    switch (blockIdx.y) {
        case 0:  src = x;  dst = g_xr;             n4 = M * E / 4; break;
        case 1:  src = wq; dst = g_wr + 0 * E * E; n4 = E * E / 4; break;
        case 2:  src = wk; dst = g_wr + 1 * E * E; n4 = E * E / 4; break;
        case 3:  src = wv; dst = g_wr + 2 * E * E; n4 = E * E / 4; break;
        default: src = wo; dst = g_wr + 3 * E * E; n4 = E * E / 4; break;
    }
    const int i = blockIdx.x * 256 + threadIdx.x;
    if (i < n4) {
        float4 v = ((const float4*)src)[i];
        v.x = tf32r(v.x); v.y = tf32r(v.y); v.z = tf32r(v.z); v.w = tf32r(v.w);
        ((float4*)dst)[i] = v;
    }
}

// ---------------------------------------------------------------------------
// Tensor-core flash attention.
// CTA: 128 q-rows x one (b,h). 8 warps, warp w owns q rows [16w,16w+16).
// K: row-major [128 kv][64 d] smem, 16B-swizzled (w ^ (row&7)), cp.async fill,
//    ldmatrix fragment loads.
// V: row-major [128 kv][72 pad] smem, cp.async fill, LDS.32 fragment loads.
// Mask: [128][132 pad] smem, cp.async fill.
// P: warp-private rows (unchanged from R4).
// ---------------------------------------------------------------------------
constexpr int PROW   = 132;
constexpr int VROW   = 72;                          // floats (pad for banks)
constexpr int SM_K   = 0;                           // 128 * 256B = 32768
constexpr int SM_V   = 32768;                       // 128 * 288B = 36864
constexpr int SM_P   = SM_V + 128 * VROW * 4;       // 69632
constexpr int SM_MSK = SM_P + 8 * 16 * PROW * 4;    // 137216
constexpr int AT_SMEM = SM_MSK + 128 * PROW * 4;    // 204800

__global__ __launch_bounds__(256, 1) void attn_mma_kernel(const float* __restrict__ mask)
{
    extern __shared__ __align__(16) char sm[];
    const uint32_t sb = smem_u32(sm);
    float* Psm = (float*)(sm + SM_P);
    float* Msm = (float*)(sm + SM_MSK);

    const int tid  = threadIdx.x;
    const int lane = tid & 31;
    const int w    = tid >> 5;
    const int r    = lane >> 2;
    const int j    = lane & 3;
    const int q0   = blockIdx.x * 128;
    const int h    = blockIdx.y;
    const int b    = blockIdx.z;

    // Prologue: Q tile -> A-frag smem (staged in P region) -> registers.
    {
        char* bufQ = (char*)Psm;
#pragma unroll
        for (int i = 0; i < 8; i++) {
            const int idx = tid + 256 * i;
            const int row = idx >> 4, d0 = (idx & 15) * 4;
            float4 v = *(const float4*)&g_q[(size_t)(b * T + q0 + row) * E + h * Dh + d0];
            stsA_g<8>(bufQ, row, d0, v);
        }
    }
    __syncthreads();
    uint32_t qa[8][4];
    {
        const char* bufQ = (const char*)Psm;
#pragma unroll
        for (int fk = 0; fk < 8; fk++) {
            uint4 t = *(const uint4*)(bufQ + (w * 8 + fk) * A_STRIDE + lane * 16);
            qa[fk][0] = t.x; qa[fk][1] = t.y; qa[fk][2] = t.z; qa[fk][3] = t.w;
        }
    }

    // K ldmatrix lane geometry.
    const int rB = (lane & 7) | ((lane & 16) >> 1);
    const int hB = (lane >> 3) & 1;
    int krow[8], kxor[8];
#pragma unroll
    for (int p = 0; p < 8; p++) {
        krow[p] = p * 16 + rB;
        kxor[p] = krow[p] & 7;
    }
    // V LDS geometry.
    const uint32_t vbase0 = sb + SM_V + j * (VROW * 4) + r * 4;

    float oo[8][4];
#pragma unroll
    for (int fn = 0; fn < 8; fn++)
#pragma unroll
        for (int k = 0; k < 4; k++) oo[fn][k] = 0.0f;

    const float NEG_INF = __int_as_float(0xff800000u);
    float mrow0 = NEG_INF, mrow1 = NEG_INF;
    float lrow0 = 0.0f,    lrow1 = 0.0f;

    for (int s0 = 0; s0 < T; s0 += 128) {
        __syncthreads();   // previous tile (K/V/mask/P) fully consumed

        // cp.async fills: K (8 x 16B/thread), V (8), mask (16).
#pragma unroll
        for (int i = 0; i < 8; i++) {
            const int idx = tid + 256 * i;
            const int row = idx >> 4, wd = idx & 15;
            const size_t g = (size_t)(b * T + s0 + row) * E + h * Dh + wd * 4;
            CP16(sb + SM_K + row * 256 + ((wd ^ (row & 7)) * 16), &g_k[g]);
            CP16(sb + SM_V + row * (VROW * 4) + wd * 16,          &g_v[g]);
        }
#pragma unroll
        for (int i = 0; i < 16; i++) {
            const int idx = tid + 256 * i;
            const int row = idx >> 5, c4 = idx & 31;
            CP16(sb + SM_MSK + row * (PROW * 4) + c4 * 16,
                 &mask[((size_t)b * T + q0 + row) * T + s0 + c4 * 4]);
        }
        CP_COMMIT();
        CP_WAIT(0);
        __syncthreads();

        // S = Q K^T  (tf32 mma; K frags via ldmatrix)
        float sc[16][4];
#pragma unroll
        for (int fn = 0; fn < 16; fn++)
#pragma unroll
            for (int k = 0; k < 4; k++) sc[fn][k] = 0.0f;

#pragma unroll
        for (int fk = 0; fk < 8; fk++) {
#pragma unroll
            for (int p = 0; p < 8; p++) {
                uint32_t k0, k1, k2, k3;
                const int sw = (2 * fk + hB) ^ kxor[p];
                LDMX4(k0, k1, k2, k3, sb + SM_K + krow[p] * 256 + sw * 16);
                uint32_t b0[2] = {k0, k1}, b1[2] = {k2, k3};
                mma_tf32(sc[2 * p],     qa[fk], b0);
                mma_tf32(sc[2 * p + 1], qa[fk], b1);
            }
        }

        // Mask add + running row max.
        float ml0 = NEG_INF, ml1 = NEG_INF;
#pragma unroll
        for (int fn = 0; fn < 16; fn++) {
            const int c0 = 8 * fn + 2 * j;
            float2 mk0 = *(const float2*)&Msm[r * PROW + c0];
            float2 mk1 = *(const float2*)&Msm[(r + 8) * PROW + c0];
            sc[fn][0] += mk0.x; sc[fn][1] += mk0.y;
            sc[fn][2] += mk1.x; sc[fn][3] += mk1.y;
            ml0 = fmaxf(ml0, fmaxf(sc[fn][0], sc[fn][1]));
            ml1 = fmaxf(ml1, fmaxf(sc[fn][2], sc[fn][3]));
        }
        ml0 = fmaxf(ml0, __shfl_xor_sync(0xffffffffu, ml0, 1));
        ml0 = fmaxf(ml0, __shfl_xor_sync(0xffffffffu, ml0, 2));
        ml1 = fmaxf(ml1, __shfl_xor_sync(0xffffffffu, ml1, 1));
        ml1 = fmaxf(ml1, __shfl_xor_sync(0xffffffffu, ml1, 2));

        const float mnew0 = fmaxf(mrow0, ml0);
        const float mnew1 = fmaxf(mrow1, ml1);
        const float alpha0 = __expf(mrow0 - mnew0);
        const float alpha1 = __expf(mrow1 - mnew1);
        mrow0 = mnew0; mrow1 = mnew1;

        // exp, P store (warp-private), l partial sums.
        float* Pw = Psm + w * 16 * PROW;
        float ls0 = 0.0f, ls1 = 0.0f;
#pragma unroll
        for (int fn = 0; fn < 16; fn++) {
            const int c0 = 8 * fn + 2 * j;
            float p0 = __expf(sc[fn][0] - mnew0);
            float p1 = __expf(sc[fn][1] - mnew0);
            float p2 = __expf(sc[fn][2] - mnew1);
            float p3 = __expf(sc[fn][3] - mnew1);
            ls0 += p0 + p1;
            ls1 += p2 + p3;
            uint2 u0 = {tf32u(p0), tf32u(p1)};
            uint2 u1 = {tf32u(p2), tf32u(p3)};
            *(uint2*)&Pw[r * PROW + c0]       = u0;
            *(uint2*)&Pw[(r + 8) * PROW + c0] = u1;
        }
        ls0 += __shfl_xor_sync(0xffffffffu, ls0, 1);
        ls0 += __shfl_xor_sync(0xffffffffu, ls0, 2);
        ls1 += __shfl_xor_sync(0xffffffffu, ls1, 1);
        ls1 += __shfl_xor_sync(0xffffffffu, ls1, 2);
        lrow0 = lrow0 * alpha0 + ls0;
        lrow1 = lrow1 * alpha1 + ls1;

#pragma unroll
        for (int fn = 0; fn < 8; fn++) {
            oo[fn][0] *= alpha0; oo[fn][1] *= alpha0;
            oo[fn][2] *= alpha1; oo[fn][3] *= alpha1;
        }
        __syncwarp();

        // O += P V   (A = P from warp-private smem, B = V via LDS.32)
        const uint32_t* Pu = (const uint32_t*)Pw;
        const float* Vf = (const float*)(sm + SM_V);
#pragma unroll
        for (int fk = 0; fk < 16; fk++) {
            uint32_t pa[4];
            pa[0] = Pu[r * PROW + 8 * fk + j];
            pa[1] = Pu[(r + 8) * PROW + 8 * fk + j];
            pa[2] = Pu[r * PROW + 8 * fk + j + 4];
            pa[3] = Pu[(r + 8) * PROW + 8 * fk + j + 4];
            const int sBase = fk * 8 + j;     // kv row for b0
#pragma unroll
            for (int fn = 0; fn < 8; fn++) {
                const int d = fn * 8 + r;
                uint32_t bb[2];
                bb[0] = tf32u(Vf[sBase * VROW + d]);
                bb[1] = tf32u(Vf[(sBase + 4) * VROW + d]);
                mma_tf32(oo[fn], pa, bb);
            }
        }
    }

    // Epilogue: normalize; ctx is tf32-rounded (feeds tf32 oproj via cp.async).
    const float inv0 = 1.0f / lrow0;
    const float inv1 = 1.0f / lrow1;
    const size_t row0 = (size_t)(b * T + q0 + w * 16 + r);
#pragma unroll
    for (int fn = 0; fn < 8; fn++) {
        const int d = h * Dh + 8 * fn + 2 * j;
        float2 v0 = {tf32r(oo[fn][0] * inv0), tf32r(oo[fn][1] * inv0)};
        float2 v1 = {tf32r(oo[fn][2] * inv1), tf32r(oo[fn][3] * inv1)};
        *(float2*)&g_ctx[row0 * E + d]       = v0;
        *(float2*)&g_ctx[(row0 + 8) * E + d] = v1;
    }
}

// ---------------------------------------------------------------------------
// Launch.
// ---------------------------------------------------------------------------
extern "C" void kernel_launch(void* const* d_in, const int* in_sizes, int n_in,
                              void* d_out, int out_size)
{
    const float* x    = (const float*)d_in[0];
    const float* mask = (const float*)d_in[1];
    const float* Wq   = (const float*)d_in[2];
    const float* bq   = (const float*)d_in[3];
    const float* Wk   = (const float*)d_in[4];
    const float* bk   = (const float*)d_in[5];
    const float* Wv   = (const float*)d_in[6];
    const float* bv   = (const float*)d_in[7];
    const float* Wo   = (const float*)d_in[8];
    const float* bo   = (const float*)d_in[9];
    float* out = (float*)d_out;

    cudaFuncSetAttribute(qkv_mma_kernel,
                         cudaFuncAttributeMaxDynamicSharedMemorySize, GEMM_SMEM);
    cudaFuncSetAttribute(oproj_mma_kernel,
                         cudaFuncAttributeMaxDynamicSharedMemorySize, GEMM_SMEM);
    cudaFuncSetAttribute(attn_mma_kernel,
                         cudaFuncAttributeMaxDynamicSharedMemorySize, AT_SMEM);

    // 1) tf32-RN pre-round (X + 4 weights) in one launch.
    round5_kernel<<<dim3(M * E / 4 / 256, 5), 256>>>(x, Wq, Wk, Wv, Wo);

    // 2) QKV projections (cp.async + ldmatrix tf32 mma): (8, 32, 3).
    qkv_mma_kernel<<<dim3(E / 128, M / 128, 3), 256, GEMM_SMEM>>>(bq, bk, bv);

    // 3) Tensor-core flash attention: (8, 16, 4).
    attn_mma_kernel<<<dim3(T / 128, H, B), 256, AT_SMEM>>>(mask);

    // 4) Output projection: (8, 32).
    oproj_mma_kernel<<<dim3(E / 128, M / 128, 1), 256, GEMM_SMEM>>>(bo, out);
}

// round 6
// speedup vs baseline: 3.5548x; 1.1599x over previous
#include <cuda_runtime.h>
#include <math.h>
#include <stdint.h>

// Problem constants.
constexpr int B  = 4;
constexpr int T  = 1024;
constexpr int E  = 1024;
constexpr int H  = 16;
constexpr int Dh = 64;
constexpr int M  = B * T;   // 4096

// Scratch (__device__ globals; no allocations allowed).
__device__ float g_q[M * E];
__device__ float g_k[M * E];
__device__ float g_v[M * E];
__device__ float g_ctx[M * E];
__device__ float g_xr[M * E];       // tf32-rounded X
__device__ float g_wr[4 * E * E];   // tf32-rounded Wq,Wk,Wv,Wo

// ---------------------------------------------------------------------------
// Helpers (family-generic PTX only: mma.sync, ldmatrix, cp.async).
// ---------------------------------------------------------------------------
__device__ __forceinline__ uint32_t smem_u32(const void* p) {
    uint32_t a;
    asm("{ .reg .u64 t; cvta.to.shared.u64 t, %1; cvt.u32.u64 %0, t; }" : "=r"(a) : "l"(p));
    return a;
}
__device__ __forceinline__ uint32_t tf32u(float x) {
    uint32_t u;
    asm("cvt.rn.tf32.f32 %0, %1;" : "=r"(u) : "f"(x));
    return u;
}
__device__ __forceinline__ float tf32r(float x) {
    return __uint_as_float(tf32u(x));
}

__device__ __forceinline__ void mma_tf32(float c[4], const uint32_t a[4],
                                         const uint32_t b[2])
{
    asm volatile(
        "mma.sync.aligned.m16n8k8.row.col.f32.tf32.tf32.f32 "
        "{%0,%1,%2,%3}, {%4,%5,%6,%7}, {%8,%9}, {%0,%1,%2,%3};"
        : "+f"(c[0]), "+f"(c[1]), "+f"(c[2]), "+f"(c[3])
        : "r"(a[0]), "r"(a[1]), "r"(a[2]), "r"(a[3]), "r"(b[0]), "r"(b[1]));
}

#define LDMX4(r0, r1, r2, r3, addr)                                        \
    asm volatile("ldmatrix.sync.aligned.m8n8.x4.shared.b16 {%0,%1,%2,%3}, [%4];" \
        : "=r"(r0), "=r"(r1), "=r"(r2), "=r"(r3) : "r"(addr))

#define CP16(dst, src) \
    asm volatile("cp.async.cg.shared.global [%0], [%1], 16;" :: "r"(dst), "l"(src))
#define CP_COMMIT() asm volatile("cp.async.commit_group;" ::: "memory")
#define CP_WAIT(n)  asm volatile("cp.async.wait_group %0;" :: "n"(n) : "memory")

// Legacy fragment-major A scatter (used only for the small Q prologue).
constexpr int A_STRIDE = 528;
template <int FKN>
__device__ __forceinline__ void stsA_g(char* base, int m, int k4, float4 v) {
    const int fm = m >> 4, fk = k4 >> 3, mr = m & 15;
    const int reg = (mr >> 3) + ((k4 & 4) >> 1);
    char* p = base + (fm * FKN + fk) * A_STRIDE + (mr & 7) * 64 + reg * 4;
    *(uint32_t*)(p +  0) = tf32u(v.x);
    *(uint32_t*)(p + 16) = tf32u(v.y);
    *(uint32_t*)(p + 32) = tf32u(v.z);
    *(uint32_t*)(p + 48) = tf32u(v.w);
}

// ---------------------------------------------------------------------------
// tf32 GEMM, cp.async 3-stage pipeline + ldmatrix, 2 CTAs/SM.
//   C[m][n] = (sum_k A[m][k]*W[n][k] + bias[n]) * scale
// CTA 128x128, BK=16, 256 threads, warps 2x4, warp tile 64x32.
// SMEM: per stage A[128][16] + B[128][16] fp32 row-major, 16B-swizzled:
//   word w of row r lives at w ^ ((r>>1)&3).
// ---------------------------------------------------------------------------
constexpr int GA_BYTES = 128 * 16 * 4;      // 8192
constexpr int GSTG     = 2 * GA_BYTES;      // 16384
constexpr int GSTAGES  = 3;
constexpr int GEMM_SMEM = GSTAGES * GSTG;   // 49152
constexpr int GKITERS  = E / 16;            // 64

template <bool RND>
__device__ __forceinline__ void gemm_cp(
    const float* __restrict__ A, const float* __restrict__ W,
    const float* __restrict__ bias, float* __restrict__ C, float scale)
{
    extern __shared__ __align__(16) char gsm[];
    const uint32_t sb = smem_u32(gsm);

    const int tid  = threadIdx.x;
    const int lane = tid & 31;
    const int wid  = tid >> 5;
    const int wm   = wid >> 2;
    const int wn   = wid & 3;
    const int bm   = blockIdx.y * 128;
    const int bn   = blockIdx.x * 128;

    // cp.async fill coords: thread covers rows crow and crow+64, word cw.
    const int crow = tid >> 2;
    const int cw   = tid & 3;
    const float* Asrc0 = A + (size_t)(bm + crow) * E + cw * 4;
    const float* Asrc1 = A + (size_t)(bm + crow + 64) * E + cw * 4;
    const float* Wsrc0 = W + (size_t)(bn + crow) * E + cw * 4;
    const float* Wsrc1 = W + (size_t)(bn + crow + 64) * E + cw * 4;
    const uint32_t dA0 = sb + crow * 64        + (cw ^ ((crow >> 1) & 3)) * 16;
    const uint32_t dA1 = sb + (crow + 64) * 64 + (cw ^ (((crow + 64) >> 1) & 3)) * 16;

    // ldmatrix lane geometry.
    const int rA = lane & 15, hA = lane >> 4;
    const int rB = (lane & 7) | ((lane & 16) >> 1);
    const int hB = (lane >> 3) & 1;
    int arow[4], axor[4];
#pragma unroll
    for (int im = 0; im < 4; im++) {
        arow[im] = wm * 64 + im * 16 + rA;
        axor[im] = (arow[im] >> 1) & 3;
    }
    int brow[2], bxor[2];
#pragma unroll
    for (int p = 0; p < 2; p++) {
        brow[p] = wn * 32 + p * 16 + rB;
        bxor[p] = (brow[p] >> 1) & 3;
    }

    float c[4][4][4];
#pragma unroll
    for (int i = 0; i < 4; i++)
#pragma unroll
        for (int j = 0; j < 4; j++)
#pragma unroll
            for (int r = 0; r < 4; r++) c[i][j][r] = 0.0f;

    // Prologue: stages 0..1.
#pragma unroll
    for (int st = 0; st < 2; st++) {
        const uint32_t base = st * GSTG;
        const int koff = st * 16;
        CP16(dA0 + base,            Asrc0 + koff);
        CP16(dA1 + base,            Asrc1 + koff);
        CP16(dA0 + base + GA_BYTES, Wsrc0 + koff);
        CP16(dA1 + base + GA_BYTES, Wsrc1 + koff);
        CP_COMMIT();
    }

    int scur = 0, snxt = 2;
    for (int it = 0; it < GKITERS; it++) {
        if (it >= GKITERS - 2) CP_WAIT(0);
        else                   CP_WAIT(1);
        __syncthreads();

        if (it + 2 < GKITERS) {
            const uint32_t base = snxt * GSTG;
            const int koff = (it + 2) * 16;
            CP16(dA0 + base,            Asrc0 + koff);
            CP16(dA1 + base,            Asrc1 + koff);
            CP16(dA0 + base + GA_BYTES, Wsrc0 + koff);
            CP16(dA1 + base + GA_BYTES, Wsrc1 + koff);
            CP_COMMIT();
        }

        const uint32_t abase = sb + scur * GSTG;
        const uint32_t bbase = abase + GA_BYTES;
#pragma unroll
        for (int fk = 0; fk < 2; fk++) {
            uint32_t a[4][4], b[4][2];
#pragma unroll
            for (int im = 0; im < 4; im++) {
                const int sw = (2 * fk + hA) ^ axor[im];
                LDMX4(a[im][0], a[im][1], a[im][2], a[im][3],
                      abase + arow[im] * 64 + sw * 16);
            }
#pragma unroll
            for (int p = 0; p < 2; p++) {
                const int sw = (2 * fk + hB) ^ bxor[p];
                LDMX4(b[2 * p][0], b[2 * p][1], b[2 * p + 1][0], b[2 * p + 1][1],
                      bbase + brow[p] * 64 + sw * 16);
            }
#pragma unroll
            for (int im = 0; im < 4; im++)
#pragma unroll
                for (int in = 0; in < 4; in++)
                    mma_tf32(c[im][in], a[im], b[in]);
        }
        scur = (scur == 2) ? 0 : scur + 1;
        snxt = (snxt == 2) ? 0 : snxt + 1;
    }

    // Epilogue.
    const int r0 = lane >> 2;
    const int cl = 2 * (lane & 3);
#pragma unroll
    for (int im = 0; im < 4; im++) {
        const int row = bm + wm * 64 + im * 16 + r0;
#pragma unroll
        for (int in = 0; in < 4; in++) {
            const int col = bn + wn * 32 + in * 8 + cl;
            const float bb0 = bias[col], bb1 = bias[col + 1];
            float2 o0, o1;
            o0.x = (c[im][in][0] + bb0) * scale;
            o0.y = (c[im][in][1] + bb1) * scale;
            o1.x = (c[im][in][2] + bb0) * scale;
            o1.y = (c[im][in][3] + bb1) * scale;
            if (RND) {
                o0.x = tf32r(o0.x); o0.y = tf32r(o0.y);
                o1.x = tf32r(o1.x); o1.y = tf32r(o1.y);
            }
            *(float2*)&C[(size_t)row * E + col]       = o0;
            *(float2*)&C[(size_t)(row + 8) * E + col] = o1;
        }
    }
}

__global__ __launch_bounds__(256, 2) void qkv_mma_kernel(
    const float* __restrict__ bq, const float* __restrict__ bk,
    const float* __restrict__ bv)
{
    const int z = blockIdx.z;
    const float* W    = g_wr + (size_t)z * E * E;
    const float* bias = (z == 0) ? bq : ((z == 1) ? bk : bv);
    float*       C    = (z == 0) ? g_q : ((z == 1) ? g_k : g_v);
    const float scale = (z == 0) ? 0.125f : 1.0f;     // Dh^-0.5
    gemm_cp<true>(g_xr, W, bias, C, scale);
}

__global__ __launch_bounds__(256, 2) void oproj_mma_kernel(
    const float* __restrict__ bo, float* __restrict__ out)
{
    gemm_cp<false>(g_ctx, g_wr + (size_t)3 * E * E, bo, out, 1.0f);
}

// ---------------------------------------------------------------------------
// tf32-RN pre-round of X and the 4 weight matrices (one launch).
// ---------------------------------------------------------------------------
__global__ __launch_bounds__(256) void round5_kernel(
    const float* __restrict__ x,  const float* __restrict__ wq,
    const float* __restrict__ wk, const float* __restrict__ wv,
    const float* __restrict__ wo)
{
    const float* src; float* dst; int n4;
    switch (blockIdx.y) {
        case 0:  src = x;  dst = g_xr;             n4 = M * E / 4; break;
        case 1:  src = wq; dst = g_wr + 0 * E * E; n4 = E * E / 4; break;
        case 2:  src = wk; dst = g_wr + 1 * E * E; n4 = E * E / 4; break;
        case 3:  src = wv; dst = g_wr + 2 * E * E; n4 = E * E / 4; break;
        default: src = wo; dst = g_wr + 3 * E * E; n4 = E * E / 4; break;
    }
    const int i = blockIdx.x * 256 + threadIdx.x;
    if (i < n4) {
        float4 v = ((const float4*)src)[i];
        v.x = tf32r(v.x); v.y = tf32r(v.y); v.z = tf32r(v.z); v.w = tf32r(v.w);
        ((float4*)dst)[i] = v;
    }
}

// ---------------------------------------------------------------------------
// Tensor-core flash attention, double-buffered K/V, mask via direct LDG.
// CTA: 128 q-rows x one (b,h). 8 warps, warp w owns q rows [16w,16w+16).
// K: row-major [128 kv][64 d], 16B-swizzled (w ^ (row&7)), ldmatrix loads.
// V: row-major [128 kv][72 pad], LDS.32 fragment loads.
// P: warp-private rows.
// ---------------------------------------------------------------------------
constexpr int PROW    = 132;
constexpr int VROW    = 72;                         // floats (bank pad)
constexpr int KBUF    = 128 * 256;                  // 32768
constexpr int VBUF    = 128 * VROW * 4;             // 36864
constexpr int SM_K    = 0;                          // 2 bufs
constexpr int SM_V    = 2 * KBUF;                   // 65536, 2 bufs
constexpr int SM_P    = SM_V + 2 * VBUF;            // 139264
constexpr int AT_SMEM = SM_P + 8 * 16 * PROW * 4;   // 206848
constexpr int NTILES  = T / 128;                    // 8

__global__ __launch_bounds__(256, 1) void attn_mma_kernel(const float* __restrict__ mask)
{
    extern __shared__ __align__(16) char sm[];
    const uint32_t sb = smem_u32(sm);
    float* Psm = (float*)(sm + SM_P);

    const int tid  = threadIdx.x;
    const int lane = tid & 31;
    const int w    = tid >> 5;
    const int r    = lane >> 2;
    const int j    = lane & 3;
    const int q0   = blockIdx.x * 128;
    const int h    = blockIdx.y;
    const int b    = blockIdx.z;

    // Per-thread fill coords (reused every tile).
    int frow[8], fwd[8];
    uint32_t kdst[8], vdst[8];
    const float* ksrc[8];
    const float* vsrc[8];
#pragma unroll
    for (int i = 0; i < 8; i++) {
        const int idx = tid + 256 * i;
        frow[i] = idx >> 4; fwd[i] = idx & 15;
        kdst[i] = sb + SM_K + frow[i] * 256 + ((fwd[i] ^ (frow[i] & 7)) * 16);
        vdst[i] = sb + SM_V + frow[i] * (VROW * 4) + fwd[i] * 16;
        const size_t g = (size_t)(b * T + frow[i]) * E + h * Dh + fwd[i] * 4;
        ksrc[i] = &g_k[g];
        vsrc[i] = &g_v[g];
    }

    // Issue tile 0 fills immediately (overlaps with Q prologue).
#pragma unroll
    for (int i = 0; i < 8; i++) {
        CP16(kdst[i], ksrc[i]);
        CP16(vdst[i], vsrc[i]);
    }
    CP_COMMIT();

    // Prologue: Q tile -> A-frag smem (staged in P region) -> registers.
    {
        char* bufQ = (char*)Psm;
#pragma unroll
        for (int i = 0; i < 8; i++) {
            const int idx = tid + 256 * i;
            const int row = idx >> 4, d0 = (idx & 15) * 4;
            float4 v = *(const float4*)&g_q[(size_t)(b * T + q0 + row) * E + h * Dh + d0];
            stsA_g<8>(bufQ, row, d0, v);
        }
    }
    __syncthreads();
    uint32_t qa[8][4];
    {
        const char* bufQ = (const char*)Psm;
#pragma unroll
        for (int fk = 0; fk < 8; fk++) {
            uint4 t = *(const uint4*)(bufQ + (w * 8 + fk) * A_STRIDE + lane * 16);
            qa[fk][0] = t.x; qa[fk][1] = t.y; qa[fk][2] = t.z; qa[fk][3] = t.w;
        }
    }

    // K ldmatrix lane geometry.
    const int rB = (lane & 7) | ((lane & 16) >> 1);
    const int hB = (lane >> 3) & 1;
    int krow[8], kxor[8];
#pragma unroll
    for (int p = 0; p < 8; p++) {
        krow[p] = p * 16 + rB;
        kxor[p] = krow[p] & 7;
    }

    // Mask row base for this thread (rows w*16+r and +8).
    const float* mrow = mask + ((size_t)b * T + q0 + w * 16 + r) * T;

    float oo[8][4];
#pragma unroll
    for (int fn = 0; fn < 8; fn++)
#pragma unroll
        for (int k = 0; k < 4; k++) oo[fn][k] = 0.0f;

    const float NEG_INF = __int_as_float(0xff800000u);
    float mrow0 = NEG_INF, mrow1 = NEG_INF;
    float lrow0 = 0.0f,    lrow1 = 0.0f;

    for (int t = 0; t < NTILES; t++) {
        const int cur = t & 1;
        CP_WAIT(0);          // tile t's fills complete
        __syncthreads();     // all threads past tile t-1 compute

        // Issue tile t+1 into the alternate buffers (overlaps compute below).
        if (t + 1 < NTILES) {
            const int alt = (t + 1) & 1;
            const int soff = (t + 1) * 128 * E;      // advance 128 kv rows
#pragma unroll
            for (int i = 0; i < 8; i++) {
                CP16(kdst[i] + alt * KBUF, ksrc[i] + soff);
                CP16(vdst[i] + alt * VBUF, vsrc[i] + soff);
            }
            CP_COMMIT();
        }

        const uint32_t kb = sb + SM_K + cur * KBUF;
        const float*   Vf = (const float*)(sm + SM_V + cur * VBUF);
        const int s0 = t * 128;

        // S = Q K^T  (tf32 mma; K frags via ldmatrix)
        float sc[16][4];
#pragma unroll
        for (int fn = 0; fn < 16; fn++)
#pragma unroll
            for (int k = 0; k < 4; k++) sc[fn][k] = 0.0f;

#pragma unroll
        for (int fk = 0; fk < 8; fk++) {
#pragma unroll
            for (int p = 0; p < 8; p++) {
                uint32_t k0, k1, k2, k3;
                const int sw = (2 * fk + hB) ^ kxor[p];
                LDMX4(k0, k1, k2, k3, kb + krow[p] * 256 + sw * 16);
                uint32_t b0[2] = {k0, k1}, b1[2] = {k2, k3};
                mma_tf32(sc[2 * p],     qa[fk], b0);
                mma_tf32(sc[2 * p + 1], qa[fk], b1);
            }
        }

        // Mask add (direct LDG, L2-resident) + running row max.
        const float* mp = mrow + s0;
        float ml0 = NEG_INF, ml1 = NEG_INF;
#pragma unroll
        for (int fn = 0; fn < 16; fn++) {
            const int c0 = 8 * fn + 2 * j;
            float2 mk0 = *(const float2*)&mp[c0];
            float2 mk1 = *(const float2*)&mp[8 * T + c0];
            sc[fn][0] += mk0.x; sc[fn][1] += mk0.y;
            sc[fn][2] += mk1.x; sc[fn][3] += mk1.y;
            ml0 = fmaxf(ml0, fmaxf(sc[fn][0], sc[fn][1]));
            ml1 = fmaxf(ml1, fmaxf(sc[fn][2], sc[fn][3]));
        }
        ml0 = fmaxf(ml0, __shfl_xor_sync(0xffffffffu, ml0, 1));
        ml0 = fmaxf(ml0, __shfl_xor_sync(0xffffffffu, ml0, 2));
        ml1 = fmaxf(ml1, __shfl_xor_sync(0xffffffffu, ml1, 1));
        ml1 = fmaxf(ml1, __shfl_xor_sync(0xffffffffu, ml1, 2));

        const float mnew0 = fmaxf(mrow0, ml0);
        const float mnew1 = fmaxf(mrow1, ml1);
        const float alpha0 = __expf(mrow0 - mnew0);
        const float alpha1 = __expf(mrow1 - mnew1);
        mrow0 = mnew0; mrow1 = mnew1;

        // exp, P store (warp-private), l partial sums.
        float* Pw = Psm + w * 16 * PROW;
        float ls0 = 0.0f, ls1 = 0.0f;
#pragma unroll
        for (int fn = 0; fn < 16; fn++) {
            const int c0 = 8 * fn + 2 * j;
            float p0 = __expf(sc[fn][0] - mnew0);
            float p1 = __expf(sc[fn][1] - mnew0);
            float p2 = __expf(sc[fn][2] - mnew1);
            float p3 = __expf(sc[fn][3] - mnew1);
            ls0 += p0 + p1;
            ls1 += p2 + p3;
            uint2 u0 = {tf32u(p0), tf32u(p1)};
            uint2 u1 = {tf32u(p2), tf32u(p3)};
            *(uint2*)&Pw[r * PROW + c0]       = u0;
            *(uint2*)&Pw[(r + 8) * PROW + c0] = u1;
        }
        ls0 += __shfl_xor_sync(0xffffffffu, ls0, 1);
        ls0 += __shfl_xor_sync(0xffffffffu, ls0, 2);
        ls1 += __shfl_xor_sync(0xffffffffu, ls1, 1);
        ls1 += __shfl_xor_sync(0xffffffffu, ls1, 2);
        lrow0 = lrow0 * alpha0 + ls0;
        lrow1 = lrow1 * alpha1 + ls1;

#pragma unroll
        for (int fn = 0; fn < 8; fn++) {
            oo[fn][0] *= alpha0; oo[fn][1] *= alpha0;
            oo[fn][2] *= alpha1; oo[fn][3] *= alpha1;
        }
        __syncwarp();

        // O += P V   (A = P from warp-private smem, B = V via LDS.32)
        const uint32_t* Pu = (const uint32_t*)Pw;
#pragma unroll
        for (int fk = 0; fk < 16; fk++) {
            uint32_t pa[4];
            pa[0] = Pu[r * PROW + 8 * fk + j];
            pa[1] = Pu[(r + 8) * PROW + 8 * fk + j];
            pa[2] = Pu[r * PROW + 8 * fk + j + 4];
            pa[3] = Pu[(r + 8) * PROW + 8 * fk + j + 4];
            const int sBase = fk * 8 + j;     // kv row for b0
#pragma unroll
            for (int fn = 0; fn < 8; fn++) {
                const int d = fn * 8 + r;
                uint32_t bb[2];
                bb[0] = tf32u(Vf[sBase * VROW + d]);
                bb[1] = tf32u(Vf[(sBase + 4) * VROW + d]);
                mma_tf32(oo[fn], pa, bb);
            }
        }
    }

    // Epilogue: normalize; ctx is tf32-rounded (feeds tf32 oproj via cp.async).
    const float inv0 = 1.0f / lrow0;
    const float inv1 = 1.0f / lrow1;
    const size_t row0 = (size_t)(b * T + q0 + w * 16 + r);
#pragma unroll
    for (int fn = 0; fn < 8; fn++) {
        const int d = h * Dh + 8 * fn + 2 * j;
        float2 v0 = {tf32r(oo[fn][0] * inv0), tf32r(oo[fn][1] * inv0)};
        float2 v1 = {tf32r(oo[fn][2] * inv1), tf32r(oo[fn][3] * inv1)};
        *(float2*)&g_ctx[row0 * E + d]       = v0;
        *(float2*)&g_ctx[(row0 + 8) * E + d] = v1;
    }
}

// ---------------------------------------------------------------------------
// Launch.
// ---------------------------------------------------------------------------
extern "C" void kernel_launch(void* const* d_in, const int* in_sizes, int n_in,
                              void* d_out, int out_size)
{
    const float* x    = (const float*)d_in[0];
    const float* mask = (const float*)d_in[1];
    const float* Wq   = (const float*)d_in[2];
    const float* bq   = (const float*)d_in[3];
    const float* Wk   = (const float*)d_in[4];
    const float* bk   = (const float*)d_in[5];
    const float* Wv   = (const float*)d_in[6];
    const float* bv   = (const float*)d_in[7];
    const float* Wo   = (const float*)d_in[8];
    const float* bo   = (const float*)d_in[9];
    float* out = (float*)d_out;

    cudaFuncSetAttribute(qkv_mma_kernel,
                         cudaFuncAttributeMaxDynamicSharedMemorySize, GEMM_SMEM);
    cudaFuncSetAttribute(oproj_mma_kernel,
                         cudaFuncAttributeMaxDynamicSharedMemorySize, GEMM_SMEM);
    cudaFuncSetAttribute(attn_mma_kernel,
                         cudaFuncAttributeMaxDynamicSharedMemorySize, AT_SMEM);

    // 1) tf32-RN pre-round (X + 4 weights) in one launch.
    round5_kernel<<<dim3(M * E / 4 / 256, 5), 256>>>(x, Wq, Wk, Wv, Wo);

    // 2) QKV projections (cp.async + ldmatrix tf32 mma): (8, 32, 3).
    qkv_mma_kernel<<<dim3(E / 128, M / 128, 3), 256, GEMM_SMEM>>>(bq, bk, bv);

    // 3) Tensor-core flash attention (double-buffered): (8, 16, 4).
    attn_mma_kernel<<<dim3(T / 128, H, B), 256, AT_SMEM>>>(mask);

    // 4) Output projection: (8, 32).
    oproj_mma_kernel<<<dim3(E / 128, M / 128, 1), 256, GEMM_SMEM>>>(bo, out);
}